// round 3
// baseline (speedup 1.0000x reference)
#include <cuda_runtime.h>
#include <math.h>

#define NN 50000
#define EE 800000
#define DH 256
#define DC 64

// Scratch (static device globals — allocation-free per harness rules).
__device__ float g_h0[NN * DH];      // GEMM output (pre-scaled by dinv via epilogue)
__device__ float g_h1[NN * DH];      // layer activations
__device__ float g_dinv[NN];
__device__ int   g_deg[NN];
__device__ int   g_off[NN + 1];
__device__ int   g_cur[NN];
__device__ int   g_csr[EE];
__device__ int   g_idx[2 * EE];      // normalized int32 edge indices [row | col]
__device__ int   g_is64;

// ---------------- edge-index dtype detection + normalization ----------------
// int64 little-endian with values < 2^31: every odd 32-bit word is 0.
// int32: odd words are random node ids -> virtually never all zero.
__global__ void detect_k(const int* __restrict__ w) {
    __shared__ int any;
    if (threadIdx.x == 0) any = 0;
    __syncthreads();
    if (w[2 * threadIdx.x + 1] != 0) atomicOr(&any, 1);
    __syncthreads();
    if (threadIdx.x == 0) g_is64 = (any == 0) ? 1 : 0;
}

__global__ void convert_k(const int* __restrict__ w) {
    int e = blockIdx.x * blockDim.x + threadIdx.x;
    if (e < 2 * EE) {
        int v = g_is64 ? w[2 * e] : w[e];
        // safety clamp: wrong values show as rel_err, not a crash
        if (v < 0) v = 0;
        if (v >= NN) v = NN - 1;
        g_idx[e] = v;
    }
}

// ---------------- preprocessing ----------------

__global__ void zero_deg_k() {
    int i = blockIdx.x * blockDim.x + threadIdx.x;
    if (i < NN) g_deg[i] = 0;
}

__global__ void count_k() {
    int e = blockIdx.x * blockDim.x + threadIdx.x;
    if (e < EE) atomicAdd(&g_deg[g_idx[EE + e]], 1);
}

// Single-block scan over NN degrees: builds exclusive offsets, cursors, dinv.
__global__ void scan_k() {
    __shared__ int part[1024];
    const int t = threadIdx.x;
    const int C = (NN + 1023) / 1024;  // 49
    int s0 = t * C;
    int s1 = s0 + C; if (s1 > NN) s1 = NN;
    int s = 0;
    for (int i = s0; i < s1; i++) s += g_deg[i];
    part[t] = s;
    __syncthreads();
    for (int d = 1; d < 1024; d <<= 1) {
        int v = 0;
        if (t >= d) v = part[t - d];
        __syncthreads();
        part[t] += v;
        __syncthreads();
    }
    int run = (t == 0) ? 0 : part[t - 1];
    for (int i = s0; i < s1; i++) {
        g_off[i] = run;
        g_cur[i] = run;
        g_dinv[i] = rsqrtf((float)(g_deg[i] + 1));
        run += g_deg[i];
    }
    if (t == 1023) g_off[NN] = run;
}

__global__ void scatter_k() {
    int e = blockIdx.x * blockDim.x + threadIdx.x;
    if (e < EE) {
        int c = g_idx[EE + e];
        int p = atomicAdd(&g_cur[c], 1);
        if (p < EE) g_csr[p] = g_idx[e];
    }
}

// ---------------- GEMM ----------------
// C = A @ B.  A source: EXT_A ? param `A` : g_h1.  C dest: EXT_C ? param `C` : g_h0.
// EPI 0: out = acc * g_dinv[row]   (conv pre-scale)
// EPI 1: out = sigmoid(acc + bias[col])
template <int BM, int BN, int TM, int TN, int KT, int KD, int EPI, int EXT_A, int EXT_C>
__global__ void gemm_k(const float* __restrict__ A_ext, const float* __restrict__ B,
                       const float* __restrict__ bias, float* __restrict__ C_ext,
                       int nrows, int mcols) {
    const float* A = EXT_A ? A_ext : (const float*)g_h1;
    float* C = EXT_C ? C_ext : (float*)g_h0;

    __shared__ float As[BM][KT];
    __shared__ float Bs[KT][BN];

    const int tid = threadIdx.x;           // 256 threads
    const int NTX = BN / TN;
    const int tx = tid % NTX;
    const int ty = tid / NTX;
    const int row0 = blockIdx.y * BM;
    const int col0 = blockIdx.x * BN;

    float acc[TM][TN];
#pragma unroll
    for (int i = 0; i < TM; i++)
#pragma unroll
        for (int j = 0; j < TN; j++) acc[i][j] = 0.0f;

    const int PA4 = (BM * KT) / (256 * 4);
    const int PB4 = (KT * BN) / (256 * 4);

    for (int k0 = 0; k0 < KD; k0 += KT) {
#pragma unroll
        for (int l = 0; l < PA4; l++) {
            int f = (tid + l * 256) * 4;
            int r = f / KT, kk = f % KT;
            float4 v = make_float4(0.f, 0.f, 0.f, 0.f);
            if (row0 + r < nrows)
                v = *(const float4*)&A[(size_t)(row0 + r) * KD + k0 + kk];
            *(float4*)&As[r][kk] = v;
        }
#pragma unroll
        for (int l = 0; l < PB4; l++) {
            int f = (tid + l * 256) * 4;
            int r = f / BN, cc = f % BN;
            *(float4*)&Bs[r][cc] =
                *(const float4*)&B[(size_t)(k0 + r) * mcols + col0 + cc];
        }
        __syncthreads();

#pragma unroll
        for (int k = 0; k < KT; k++) {
            float a[TM], b[TN];
#pragma unroll
            for (int i = 0; i < TM; i++) a[i] = As[ty * TM + i][k];
#pragma unroll
            for (int j = 0; j < TN; j++) b[j] = Bs[k][tx * TN + j];
#pragma unroll
            for (int i = 0; i < TM; i++)
#pragma unroll
                for (int j = 0; j < TN; j++) acc[i][j] = fmaf(a[i], b[j], acc[i][j]);
        }
        __syncthreads();
    }

#pragma unroll
    for (int i = 0; i < TM; i++) {
        int r = row0 + ty * TM + i;
        if (r >= nrows) continue;
        if (EPI == 0) {
            float sc = g_dinv[r];
#pragma unroll
            for (int j = 0; j < TN; j++)
                C[(size_t)r * mcols + col0 + tx * TN + j] = acc[i][j] * sc;
        } else {
#pragma unroll
            for (int j = 0; j < TN; j++) {
                int c = col0 + tx * TN + j;
                float v = acc[i][j] + bias[c];
                C[(size_t)r * mcols + c] = 1.0f / (1.0f + expf(-v));
            }
        }
    }
}

// ---------------- aggregation ----------------
// g_h1[c] = maybe_relu( dinv[c] * (g_h0[c] + sum_{r -> c} g_h0[r]) + bias )
// blockDim = D/4 (one float4 per thread)
template <int D, int RELU>
__global__ void agg_k(const float* __restrict__ bias) {
    const float* hs = (const float*)g_h0;
    float* out = (float*)g_h1;
    const int c = blockIdx.x;
    const int t = threadIdx.x;

    float4 acc = ((const float4*)(hs + (size_t)c * D))[t];  // self loop
    const int s = g_off[c], e = g_off[c + 1];
    for (int p = s; p < e; p++) {
        int r = __ldg(&g_csr[p]);
        float4 v = ((const float4*)(hs + (size_t)r * D))[t];
        acc.x += v.x; acc.y += v.y; acc.z += v.z; acc.w += v.w;
    }
    const float sc = g_dinv[c];
    float4 bb = ((const float4*)bias)[t];
    float4 o;
    o.x = fmaf(acc.x, sc, bb.x);
    o.y = fmaf(acc.y, sc, bb.y);
    o.z = fmaf(acc.z, sc, bb.z);
    o.w = fmaf(acc.w, sc, bb.w);
    if (RELU) {
        o.x = fmaxf(o.x, 0.f); o.y = fmaxf(o.y, 0.f);
        o.z = fmaxf(o.z, 0.f); o.w = fmaxf(o.w, 0.f);
    }
    ((float4*)(out + (size_t)c * D))[t] = o;
}

// ---------------- launch ----------------

extern "C" void kernel_launch(void* const* d_in, const int* in_sizes, int n_in,
                              void* d_out, int out_size) {
    const float* x  = (const float*)d_in[0];
    const int* eiw  = (const int*)d_in[1];   // raw words; dtype detected on device
    const float* W1 = (const float*)d_in[2];
    const float* b1 = (const float*)d_in[3];
    const float* W2 = (const float*)d_in[4];
    const float* b2 = (const float*)d_in[5];
    const float* W3 = (const float*)d_in[6];
    const float* b3 = (const float*)d_in[7];
    const float* W4 = (const float*)d_in[8];
    const float* b4 = (const float*)d_in[9];

    // normalize edge_index to int32, then degrees -> offsets/dinv -> dest-CSR
    detect_k<<<1, 256>>>(eiw);
    convert_k<<<(2 * EE + 255) / 256, 256>>>(eiw);
    zero_deg_k<<<(NN + 255) / 256, 256>>>();
    count_k<<<(EE + 255) / 256, 256>>>();
    scan_k<<<1, 1024>>>();
    scatter_k<<<(EE + 255) / 256, 256>>>();

    const dim3 g256(DH / 128, (NN + 127) / 128);   // (2, 391)
    const dim3 g64(1, (NN + 127) / 128);           // (1, 391)

    // Layer 1: 256 -> 256, relu.  A = x (ext), C = g_h0
    gemm_k<128, 128, 8, 8, 16, 256, 0, 1, 0><<<g256, 256>>>(x, W1, nullptr, nullptr, NN, DH);
    agg_k<256, 1><<<NN, 64>>>(b1);

    // Layer 2 applied 4x (shared weights), relu.  A = g_h1, C = g_h0
    for (int it = 0; it < 4; it++) {
        gemm_k<128, 128, 8, 8, 16, 256, 0, 0, 0><<<g256, 256>>>(nullptr, W2, nullptr, nullptr, NN, DH);
        agg_k<256, 1><<<NN, 64>>>(b2);
    }

    // Layer 3: 256 -> 64, no relu.  A = g_h1, C = g_h0
    gemm_k<128, 64, 8, 4, 16, 256, 0, 0, 0><<<g64, 256>>>(nullptr, W3, nullptr, nullptr, NN, DC);
    agg_k<64, 0><<<NN, 16>>>(b3);

    // Final dense 64 -> 64 + sigmoid.  A = g_h1, C = d_out (ext)
    gemm_k<128, 64, 8, 4, 16, 64, 1, 0, 1><<<g64, 256>>>(nullptr, W4, b4, (float*)d_out, NN, DC);
}

// round 5
// speedup vs baseline: 1.9371x; 1.9371x over previous
#include <cuda_runtime.h>
#include <math.h>
#include <stdint.h>

#define NN 50000
#define EE 800000
#define DH 256
#define DC 64

// ---------------- device scratch ----------------
__device__ float g_h0[NN * DH];      // GEMM output (dinv-scaled) -> agg input
__device__ float g_h1[NN * DH];      // agg output -> next GEMM A
__device__ float g_Wt1[DH * DH];     // W^T: [n][k], K contiguous
__device__ float g_Wt2[DH * DH];
__device__ float g_Wt3[DC * DH];
__device__ float g_dinv[NN];
__device__ int   g_deg[NN];
__device__ int   g_off[NN + 1];
__device__ int   g_cur[NN];
__device__ int   g_csr[EE];
__device__ int   g_idx[2 * EE];
__device__ int   g_is64;

// ---------------- PTX helpers (all plain-sm_103-legal: sm_80 era) ----------------
__device__ __forceinline__ uint32_t s2u(const void* p) {
    uint32_t a;
    asm("{ .reg .u64 t; cvta.to.shared.u64 t, %1; cvt.u32.u64 %0, t; }" : "=r"(a) : "l"(p));
    return a;
}
__device__ __forceinline__ void cp16(uint32_t dst, const void* src, bool valid) {
    int sz = valid ? 16 : 0;
    asm volatile("cp.async.ca.shared.global [%0], [%1], 16, %2;"
                 :: "r"(dst), "l"(src), "r"(sz) : "memory");
}
__device__ __forceinline__ void cp_commit() {
    asm volatile("cp.async.commit_group;" ::: "memory");
}
template <int N>
__device__ __forceinline__ void cp_wait() {
    asm volatile("cp.async.wait_group %0;" :: "n"(N) : "memory");
}
__device__ __forceinline__ void mma16n8k8(float* c, const uint32_t* a, const uint32_t* b) {
    asm volatile(
        "mma.sync.aligned.m16n8k8.row.col.f32.tf32.tf32.f32 "
        "{%0,%1,%2,%3}, {%4,%5,%6,%7}, {%8,%9}, {%0,%1,%2,%3};"
        : "+f"(c[0]), "+f"(c[1]), "+f"(c[2]), "+f"(c[3])
        : "r"(a[0]), "r"(a[1]), "r"(a[2]), "r"(a[3]), "r"(b[0]), "r"(b[1]));
}

// ---------------- edge-index dtype detection + normalization ----------------
__global__ void detect_k(const int* __restrict__ w) {
    __shared__ int any;
    if (threadIdx.x == 0) any = 0;
    __syncthreads();
    if (w[2 * threadIdx.x + 1] != 0) atomicOr(&any, 1);
    __syncthreads();
    if (threadIdx.x == 0) g_is64 = (any == 0) ? 1 : 0;
}
__global__ void convert_k(const int* __restrict__ w) {
    int e = blockIdx.x * blockDim.x + threadIdx.x;
    if (e < 2 * EE) {
        int v = g_is64 ? w[2 * e] : w[e];
        if (v < 0) v = 0;
        if (v >= NN) v = NN - 1;
        g_idx[e] = v;
    }
}

// ---------------- preprocessing ----------------
__global__ void zero_deg_k() {
    int i = blockIdx.x * blockDim.x + threadIdx.x;
    if (i < NN) g_deg[i] = 0;
}
__global__ void count_k() {
    int e = blockIdx.x * blockDim.x + threadIdx.x;
    if (e < EE) atomicAdd(&g_deg[g_idx[EE + e]], 1);
}
__global__ void scan_k() {
    __shared__ int part[1024];
    const int t = threadIdx.x;
    const int C = (NN + 1023) / 1024;
    int s0 = t * C;
    int s1 = s0 + C; if (s1 > NN) s1 = NN;
    if (s0 > NN) s0 = NN;
    int s = 0;
    for (int i = s0; i < s1; i++) s += g_deg[i];
    part[t] = s;
    __syncthreads();
    for (int d = 1; d < 1024; d <<= 1) {
        int v = 0;
        if (t >= d) v = part[t - d];
        __syncthreads();
        part[t] += v;
        __syncthreads();
    }
    int run = (t == 0) ? 0 : part[t - 1];
    for (int i = s0; i < s1; i++) {
        g_off[i] = run;
        g_cur[i] = run;
        g_dinv[i] = rsqrtf((float)(g_deg[i] + 1));
        run += g_deg[i];
    }
    if (t == 1023) g_off[NN] = run;
}
__global__ void scatter_k() {
    int e = blockIdx.x * blockDim.x + threadIdx.x;
    if (e < EE) {
        int c = g_idx[EE + e];
        int p = atomicAdd(&g_cur[c], 1);
        if (p < EE) g_csr[p] = g_idx[e];
    }
}

// ---------------- weight pre-transpose ----------------
__global__ void transpose_w_k(const float* __restrict__ W1, const float* __restrict__ W2,
                              const float* __restrict__ W3) {
    int i = blockIdx.x * blockDim.x + threadIdx.x;
    if (i < DH * DH) {
        int n = i / DH, k = i % DH;
        g_Wt1[i] = W1[k * DH + n];
        g_Wt2[i] = W2[k * DH + n];
    }
    if (i < DC * DH) {
        int n = i / DH, k = i % DH;
        g_Wt3[i] = W3[k * DC + n];
    }
}

// ---------------- tf32 mma.sync GEMM ----------------
// C[g_h0][NN, MCOLS] = A[NN, 256] @ Wt^T, epilogue: scale by dinv[row].
// CTA tile 128 x BN, 8 warps as 2(m) x 4(n), warp tile 64 x WN (WN = BN/4).
// K = 256 in 16 chunks of 16, cp.async double-buffered.
// SMEM stride 20 floats: bank = (20*m + k) % 32 -> conflict-free fragment loads.
template <int BN, int WN, int MCOLS, int EXT_A>
__global__ void __launch_bounds__(256) mma_gemm_k(const float* __restrict__ A_ext, int wsel) {
    const float* A = EXT_A ? A_ext : (const float*)g_h1;
    const float* Bt = (wsel == 0) ? (const float*)g_Wt1
                    : (wsel == 1) ? (const float*)g_Wt2
                                  : (const float*)g_Wt3;

    constexpr int ST = 20;            // SMEM row stride (floats)
    constexpr int NT = WN / 8;        // n8-tiles per warp
    __shared__ float As[2][128 * ST];
    __shared__ float Bs[2][BN * ST];

    const int tid = threadIdx.x;
    const int wid = tid >> 5;
    const int lane = tid & 31;
    const int t4 = lane >> 2;         // group id (0..7)
    const int tk = lane & 3;          // thread-in-group (0..3)
    const int wm = wid & 1;           // warp m index (0..1)
    const int wn = wid >> 1;          // warp n index (0..3)
    const int row0 = blockIdx.y * 128;
    const int col0 = blockIdx.x * BN;

    float c[4][NT][4];
#pragma unroll
    for (int mt = 0; mt < 4; mt++)
#pragma unroll
        for (int nt = 0; nt < NT; nt++)
#pragma unroll
            for (int j = 0; j < 4; j++) c[mt][nt][j] = 0.0f;

    const uint32_t sa[2] = { s2u(As[0]), s2u(As[1]) };
    const uint32_t sb[2] = { s2u(Bs[0]), s2u(Bs[1]) };

    // per-chunk load: A = 128x16 floats (512 f4, 2/thread), B = BNx16 (BN/16 per thread)
    auto load_chunk = [&](int kc, int st) {
#pragma unroll
        for (int i = 0; i < 2; i++) {
            int l = tid + i * 256;
            int m = l >> 2, k = (l & 3) * 4;
            bool v = (row0 + m) < NN;
            cp16(sa[st] + (uint32_t)(m * ST + k) * 4,
                 &A[(size_t)(row0 + m) * DH + kc * 16 + k], v);
        }
#pragma unroll
        for (int i = 0; i < BN / 64; i++) {
            int l = tid + i * 256;
            int n = l >> 2, k = (l & 3) * 4;
            cp16(sb[st] + (uint32_t)(n * ST + k) * 4,
                 &Bt[(size_t)(col0 + n) * DH + kc * 16 + k], true);
        }
        cp_commit();
    };

    load_chunk(0, 0);

    for (int kc = 0; kc < 16; kc++) {
        const int st = kc & 1;
        if (kc + 1 < 16) {
            load_chunk(kc + 1, st ^ 1);
            cp_wait<1>();
        } else {
            cp_wait<0>();
        }
        __syncthreads();

        const float* as = As[st];
        const float* bs = Bs[st];
#pragma unroll
        for (int ks = 0; ks < 2; ks++) {
            const int k0 = ks * 8;
            uint32_t a[4][4];
#pragma unroll
            for (int mt = 0; mt < 4; mt++) {
                int m = wm * 64 + mt * 16 + t4;
                a[mt][0] = __float_as_uint(as[m * ST + k0 + tk]);
                a[mt][1] = __float_as_uint(as[(m + 8) * ST + k0 + tk]);
                a[mt][2] = __float_as_uint(as[m * ST + k0 + tk + 4]);
                a[mt][3] = __float_as_uint(as[(m + 8) * ST + k0 + tk + 4]);
            }
            uint32_t b[NT][2];
#pragma unroll
            for (int nt = 0; nt < NT; nt++) {
                int n = wn * WN + nt * 8 + t4;
                b[nt][0] = __float_as_uint(bs[n * ST + k0 + tk]);
                b[nt][1] = __float_as_uint(bs[n * ST + k0 + tk + 4]);
            }
#pragma unroll
            for (int mt = 0; mt < 4; mt++)
#pragma unroll
                for (int nt = 0; nt < NT; nt++)
                    mma16n8k8(c[mt][nt], a[mt], b[nt]);
        }
        __syncthreads();
    }

    // epilogue: D fragment c0,c1 at (row t4, col 2*tk,+1); c2,c3 at row t4+8.
#pragma unroll
    for (int mt = 0; mt < 4; mt++) {
        int r0g = row0 + wm * 64 + mt * 16 + t4;
        int r1g = r0g + 8;
        float s0 = (r0g < NN) ? g_dinv[r0g] : 0.0f;
        float s1 = (r1g < NN) ? g_dinv[r1g] : 0.0f;
#pragma unroll
        for (int nt = 0; nt < NT; nt++) {
            int gc = col0 + wn * WN + nt * 8 + 2 * tk;
            if (r0g < NN) {
                float2 o0 = make_float2(c[mt][nt][0] * s0, c[mt][nt][1] * s0);
                *(float2*)&g_h0[(size_t)r0g * MCOLS + gc] = o0;
            }
            if (r1g < NN) {
                float2 o1 = make_float2(c[mt][nt][2] * s1, c[mt][nt][3] * s1);
                *(float2*)&g_h0[(size_t)r1g * MCOLS + gc] = o1;
            }
        }
    }
}

// ---------------- final dense 64->64 + sigmoid (SIMT, tiny) ----------------
template <int BM, int BN, int TM, int TN, int KT, int KD>
__global__ void gemm_sig_k(const float* __restrict__ B, const float* __restrict__ bias,
                           float* __restrict__ C, int nrows, int mcols) {
    const float* A = (const float*)g_h1;
    __shared__ float As[BM][KT];
    __shared__ float Bs[KT][BN];

    const int tid = threadIdx.x;
    const int NTX = BN / TN;
    const int tx = tid % NTX;
    const int ty = tid / NTX;
    const int row0 = blockIdx.y * BM;
    const int col0 = blockIdx.x * BN;

    float acc[TM][TN];
#pragma unroll
    for (int i = 0; i < TM; i++)
#pragma unroll
        for (int j = 0; j < TN; j++) acc[i][j] = 0.0f;

    const int PA4 = (BM * KT) / (256 * 4);
    const int PB4 = (KT * BN) / (256 * 4);

    for (int k0 = 0; k0 < KD; k0 += KT) {
#pragma unroll
        for (int l = 0; l < PA4; l++) {
            int f = (tid + l * 256) * 4;
            int r = f / KT, kk = f % KT;
            float4 v = make_float4(0.f, 0.f, 0.f, 0.f);
            if (row0 + r < nrows)
                v = *(const float4*)&A[(size_t)(row0 + r) * KD + k0 + kk];
            *(float4*)&As[r][kk] = v;
        }
#pragma unroll
        for (int l = 0; l < PB4; l++) {
            int f = (tid + l * 256) * 4;
            int r = f / BN, cc = f % BN;
            *(float4*)&Bs[r][cc] = *(const float4*)&B[(size_t)(k0 + r) * mcols + col0 + cc];
        }
        __syncthreads();
#pragma unroll
        for (int k = 0; k < KT; k++) {
            float a[TM], b[TN];
#pragma unroll
            for (int i = 0; i < TM; i++) a[i] = As[ty * TM + i][k];
#pragma unroll
            for (int j = 0; j < TN; j++) b[j] = Bs[k][tx * TN + j];
#pragma unroll
            for (int i = 0; i < TM; i++)
#pragma unroll
                for (int j = 0; j < TN; j++) acc[i][j] = fmaf(a[i], b[j], acc[i][j]);
        }
        __syncthreads();
    }

#pragma unroll
    for (int i = 0; i < TM; i++) {
        int r = row0 + ty * TM + i;
        if (r >= nrows) continue;
#pragma unroll
        for (int j = 0; j < TN; j++) {
            int c = col0 + tx * TN + j;
            float v = acc[i][j] + bias[c];
            C[(size_t)r * mcols + c] = 1.0f / (1.0f + expf(-v));
        }
    }
}

// ---------------- aggregation ----------------
template <int D, int RELU>
__global__ void agg_k(const float* __restrict__ bias) {
    const float* hs = (const float*)g_h0;
    float* out = (float*)g_h1;
    const int c = blockIdx.x;
    const int t = threadIdx.x;

    float4 acc = ((const float4*)(hs + (size_t)c * D))[t];
    const int s = g_off[c], e = g_off[c + 1];
    for (int p = s; p < e; p++) {
        int r = __ldg(&g_csr[p]);
        float4 v = ((const float4*)(hs + (size_t)r * D))[t];
        acc.x += v.x; acc.y += v.y; acc.z += v.z; acc.w += v.w;
    }
    const float sc = g_dinv[c];
    float4 bb = ((const float4*)bias)[t];
    float4 o;
    o.x = fmaf(acc.x, sc, bb.x);
    o.y = fmaf(acc.y, sc, bb.y);
    o.z = fmaf(acc.z, sc, bb.z);
    o.w = fmaf(acc.w, sc, bb.w);
    if (RELU) {
        o.x = fmaxf(o.x, 0.f); o.y = fmaxf(o.y, 0.f);
        o.z = fmaxf(o.z, 0.f); o.w = fmaxf(o.w, 0.f);
    }
    ((float4*)(out + (size_t)c * D))[t] = o;
}

// ---------------- launch ----------------
extern "C" void kernel_launch(void* const* d_in, const int* in_sizes, int n_in,
                              void* d_out, int out_size) {
    const float* x  = (const float*)d_in[0];
    const int* eiw  = (const int*)d_in[1];
    const float* W1 = (const float*)d_in[2];
    const float* b1 = (const float*)d_in[3];
    const float* W2 = (const float*)d_in[4];
    const float* b2 = (const float*)d_in[5];
    const float* W3 = (const float*)d_in[6];
    const float* b3 = (const float*)d_in[7];
    const float* W4 = (const float*)d_in[8];
    const float* b4 = (const float*)d_in[9];

    detect_k<<<1, 256>>>(eiw);
    convert_k<<<(2 * EE + 255) / 256, 256>>>(eiw);
    zero_deg_k<<<(NN + 255) / 256, 256>>>();
    count_k<<<(EE + 255) / 256, 256>>>();
    scan_k<<<1, 1024>>>();
    scatter_k<<<(EE + 255) / 256, 256>>>();
    transpose_w_k<<<256, 256>>>(W1, W2, W3);

    const int MT = (NN + 127) / 128;       // 391
    const dim3 gBig(DH / 128, MT);         // (2, 391)
    const dim3 gS(1, MT);                  // (1, 391)

    // Layer 1: 256 -> 256, relu
    mma_gemm_k<128, 32, DH, 1><<<gBig, 256>>>(x, 0);
    agg_k<256, 1><<<NN, 64>>>(b1);

    // Layer 2 x4 (shared weights), relu
    for (int it = 0; it < 4; it++) {
        mma_gemm_k<128, 32, DH, 0><<<gBig, 256>>>(nullptr, 1);
        agg_k<256, 1><<<NN, 64>>>(b2);
    }

    // Layer 3: 256 -> 64, no relu
    mma_gemm_k<64, 16, DC, 0><<<gS, 256>>>(nullptr, 2);
    agg_k<64, 0><<<NN, 16>>>(b3);

    // Final dense 64 -> 64 + sigmoid
    gemm_sig_k<128, 64, 8, 4, 16, 64><<<gS, 256>>>(W4, b4, (float*)d_out, NN, DC);
}

// round 6
// speedup vs baseline: 2.1065x; 1.0874x over previous
#include <cuda_runtime.h>
#include <cuda_fp16.h>
#include <math.h>
#include <stdint.h>

#define NN 50000
#define EE 800000
#define DH 256
#define DC 64

// ---------------- device scratch ----------------
__device__ __half g_h0h[NN * DH];    // GEMM output (dinv-scaled, fp16) -> agg gather input
__device__ float  g_h1[NN * DH];     // agg output (fp32) -> next GEMM A
__device__ float  g_Wt1[DH * DH];    // W^T: [n][k], K contiguous
__device__ float  g_Wt2[DH * DH];
__device__ float  g_Wt3[DC * DH];
__device__ float  g_dinv[NN];
__device__ int    g_deg[NN];
__device__ int    g_off[NN + 1];
__device__ int    g_cur[NN];
__device__ int    g_csr[EE];
__device__ int    g_idx[2 * EE];
__device__ int    g_is64;

// ---------------- PTX helpers (sm_80-era, plain-sm_103-legal) ----------------
__device__ __forceinline__ uint32_t s2u(const void* p) {
    uint32_t a;
    asm("{ .reg .u64 t; cvta.to.shared.u64 t, %1; cvt.u32.u64 %0, t; }" : "=r"(a) : "l"(p));
    return a;
}
__device__ __forceinline__ void cp16(uint32_t dst, const void* src, bool valid) {
    int sz = valid ? 16 : 0;
    asm volatile("cp.async.ca.shared.global [%0], [%1], 16, %2;"
                 :: "r"(dst), "l"(src), "r"(sz) : "memory");
}
__device__ __forceinline__ void cp_commit() {
    asm volatile("cp.async.commit_group;" ::: "memory");
}
template <int N>
__device__ __forceinline__ void cp_wait() {
    asm volatile("cp.async.wait_group %0;" :: "n"(N) : "memory");
}
__device__ __forceinline__ void mma16n8k8(float* c, const uint32_t* a, const uint32_t* b) {
    asm volatile(
        "mma.sync.aligned.m16n8k8.row.col.f32.tf32.tf32.f32 "
        "{%0,%1,%2,%3}, {%4,%5,%6,%7}, {%8,%9}, {%0,%1,%2,%3};"
        : "+f"(c[0]), "+f"(c[1]), "+f"(c[2]), "+f"(c[3])
        : "r"(a[0]), "r"(a[1]), "r"(a[2]), "r"(a[3]), "r"(b[0]), "r"(b[1]));
}

// ---------------- edge-index dtype detection + normalization ----------------
__global__ void detect_k(const int* __restrict__ w) {
    __shared__ int any;
    if (threadIdx.x == 0) any = 0;
    __syncthreads();
    if (w[2 * threadIdx.x + 1] != 0) atomicOr(&any, 1);
    __syncthreads();
    if (threadIdx.x == 0) g_is64 = (any == 0) ? 1 : 0;
}
__global__ void zero_deg_k() {
    int i = blockIdx.x * blockDim.x + threadIdx.x;
    if (i < NN) g_deg[i] = 0;
}
// convert + fused degree count (for col entries)
__global__ void convert_count_k(const int* __restrict__ w) {
    int e = blockIdx.x * blockDim.x + threadIdx.x;
    if (e < 2 * EE) {
        int v = g_is64 ? w[2 * e] : w[e];
        if (v < 0) v = 0;
        if (v >= NN) v = NN - 1;
        g_idx[e] = v;
        if (e >= EE) atomicAdd(&g_deg[v], 1);
    }
}
__global__ void scan_k() {
    __shared__ int part[1024];
    const int t = threadIdx.x;
    const int C = (NN + 1023) / 1024;
    int s0 = t * C;
    int s1 = s0 + C; if (s1 > NN) s1 = NN;
    if (s0 > NN) s0 = NN;
    int s = 0;
    for (int i = s0; i < s1; i++) s += g_deg[i];
    part[t] = s;
    __syncthreads();
    for (int d = 1; d < 1024; d <<= 1) {
        int v = 0;
        if (t >= d) v = part[t - d];
        __syncthreads();
        part[t] += v;
        __syncthreads();
    }
    int run = (t == 0) ? 0 : part[t - 1];
    for (int i = s0; i < s1; i++) {
        g_off[i] = run;
        g_cur[i] = run;
        g_dinv[i] = rsqrtf((float)(g_deg[i] + 1));
        run += g_deg[i];
    }
    if (t == 1023) g_off[NN] = run;
}
__global__ void scatter_k() {
    int e = blockIdx.x * blockDim.x + threadIdx.x;
    if (e < EE) {
        int c = g_idx[EE + e];
        int p = atomicAdd(&g_cur[c], 1);
        if (p < EE) g_csr[p] = g_idx[e];
    }
}

// ---------------- weight pre-transpose ----------------
__global__ void transpose_w_k(const float* __restrict__ W1, const float* __restrict__ W2,
                              const float* __restrict__ W3) {
    int i = blockIdx.x * blockDim.x + threadIdx.x;
    if (i < DH * DH) {
        int n = i / DH, k = i % DH;
        g_Wt1[i] = W1[k * DH + n];
        g_Wt2[i] = W2[k * DH + n];
    }
    if (i < DC * DH) {
        int n = i / DH, k = i % DH;
        g_Wt3[i] = W3[k * DC + n];
    }
}

// ---------------- tf32 mma.sync GEMM, fp16 epilogue ----------------
// g_h0h[NN, MCOLS] = (A[NN, 256] @ Wt^T) * dinv[row],  stored as fp16.
// CTA 128 x BN, 8 warps 2(m) x 4(n), warp tile 64 x WN. K in 16 chunks of 16,
// cp.async double-buffered. SMEM stride 20 -> conflict-free fragment LDS.
template <int BN, int WN, int MCOLS, int EXT_A>
__global__ void __launch_bounds__(256) mma_gemm_k(const float* __restrict__ A_ext, int wsel) {
    const float* A = EXT_A ? A_ext : (const float*)g_h1;
    const float* Bt = (wsel == 0) ? (const float*)g_Wt1
                    : (wsel == 1) ? (const float*)g_Wt2
                                  : (const float*)g_Wt3;

    constexpr int ST = 20;
    constexpr int NT = WN / 8;
    __shared__ float As[2][128 * ST];
    __shared__ float Bs[2][BN * ST];

    const int tid = threadIdx.x;
    const int wid = tid >> 5;
    const int lane = tid & 31;
    const int t4 = lane >> 2;
    const int tk = lane & 3;
    const int wm = wid & 1;
    const int wn = wid >> 1;
    const int row0 = blockIdx.y * 128;
    const int col0 = blockIdx.x * BN;

    float c[4][NT][4];
#pragma unroll
    for (int mt = 0; mt < 4; mt++)
#pragma unroll
        for (int nt = 0; nt < NT; nt++)
#pragma unroll
            for (int j = 0; j < 4; j++) c[mt][nt][j] = 0.0f;

    const uint32_t sa[2] = { s2u(As[0]), s2u(As[1]) };
    const uint32_t sb[2] = { s2u(Bs[0]), s2u(Bs[1]) };

    auto load_chunk = [&](int kc, int st) {
#pragma unroll
        for (int i = 0; i < 2; i++) {
            int l = tid + i * 256;
            int m = l >> 2, k = (l & 3) * 4;
            bool v = (row0 + m) < NN;
            cp16(sa[st] + (uint32_t)(m * ST + k) * 4,
                 &A[(size_t)(row0 + m) * DH + kc * 16 + k], v);
        }
#pragma unroll
        for (int i = 0; i < BN / 64; i++) {
            int l = tid + i * 256;
            int n = l >> 2, k = (l & 3) * 4;
            cp16(sb[st] + (uint32_t)(n * ST + k) * 4,
                 &Bt[(size_t)(col0 + n) * DH + kc * 16 + k], true);
        }
        cp_commit();
    };

    load_chunk(0, 0);

    for (int kc = 0; kc < 16; kc++) {
        const int st = kc & 1;
        if (kc + 1 < 16) {
            load_chunk(kc + 1, st ^ 1);
            cp_wait<1>();
        } else {
            cp_wait<0>();
        }
        __syncthreads();

        const float* as = As[st];
        const float* bs = Bs[st];
#pragma unroll
        for (int ks = 0; ks < 2; ks++) {
            const int k0 = ks * 8;
            uint32_t a[4][4];
#pragma unroll
            for (int mt = 0; mt < 4; mt++) {
                int m = wm * 64 + mt * 16 + t4;
                a[mt][0] = __float_as_uint(as[m * ST + k0 + tk]);
                a[mt][1] = __float_as_uint(as[(m + 8) * ST + k0 + tk]);
                a[mt][2] = __float_as_uint(as[m * ST + k0 + tk + 4]);
                a[mt][3] = __float_as_uint(as[(m + 8) * ST + k0 + tk + 4]);
            }
            uint32_t b[NT][2];
#pragma unroll
            for (int nt = 0; nt < NT; nt++) {
                int n = wn * WN + nt * 8 + t4;
                b[nt][0] = __float_as_uint(bs[n * ST + k0 + tk]);
                b[nt][1] = __float_as_uint(bs[n * ST + k0 + tk + 4]);
            }
#pragma unroll
            for (int mt = 0; mt < 4; mt++)
#pragma unroll
                for (int nt = 0; nt < NT; nt++)
                    mma16n8k8(c[mt][nt], a[mt], b[nt]);
        }
        __syncthreads();
    }

    // epilogue: scale by dinv, convert to fp16 pairs
#pragma unroll
    for (int mt = 0; mt < 4; mt++) {
        int r0g = row0 + wm * 64 + mt * 16 + t4;
        int r1g = r0g + 8;
        float s0 = (r0g < NN) ? g_dinv[r0g] : 0.0f;
        float s1 = (r1g < NN) ? g_dinv[r1g] : 0.0f;
#pragma unroll
        for (int nt = 0; nt < NT; nt++) {
            int gc = col0 + wn * WN + nt * 8 + 2 * tk;
            if (r0g < NN)
                *(__half2*)&g_h0h[(size_t)r0g * MCOLS + gc] =
                    __floats2half2_rn(c[mt][nt][0] * s0, c[mt][nt][1] * s0);
            if (r1g < NN)
                *(__half2*)&g_h0h[(size_t)r1g * MCOLS + gc] =
                    __floats2half2_rn(c[mt][nt][2] * s1, c[mt][nt][3] * s1);
        }
    }
}

// ---------------- aggregation (warp per node, fp16 gather, fp32 accum) ----------------
__device__ __forceinline__ void acc_add8(float* acc, uint4 v) {
    const __half2* h = (const __half2*)&v;
#pragma unroll
    for (int i = 0; i < 4; i++) {
        float2 f = __half22float2(h[i]);
        acc[2 * i] += f.x;
        acc[2 * i + 1] += f.y;
    }
}

// D = 256: lane owns 8 contiguous cols (one uint4 of halves). 8 warps/block.
template <int RELU>
__global__ void __launch_bounds__(256) agg256_k(const float* __restrict__ bias) {
    const int node = blockIdx.x * 8 + (threadIdx.x >> 5);
    if (node >= NN) return;
    const int lane = threadIdx.x & 31;
    const uint4* base = (const uint4*)g_h0h;   // row stride = 256*2/16 = 32 uint4

    float acc[8];
    uint4 v = __ldg(&base[(size_t)node * 32 + lane]);   // self loop
#pragma unroll
    for (int i = 0; i < 8; i++) acc[i] = 0.0f;
    acc_add8(acc, v);

    const int s = g_off[node], e = g_off[node + 1];
    int p = s;
    for (; p + 4 <= e; p += 4) {
        int r0 = __ldg(&g_csr[p]);
        int r1 = __ldg(&g_csr[p + 1]);
        int r2 = __ldg(&g_csr[p + 2]);
        int r3 = __ldg(&g_csr[p + 3]);
        uint4 v0 = __ldg(&base[(size_t)r0 * 32 + lane]);
        uint4 v1 = __ldg(&base[(size_t)r1 * 32 + lane]);
        uint4 v2 = __ldg(&base[(size_t)r2 * 32 + lane]);
        uint4 v3 = __ldg(&base[(size_t)r3 * 32 + lane]);
        acc_add8(acc, v0); acc_add8(acc, v1); acc_add8(acc, v2); acc_add8(acc, v3);
    }
    for (; p < e; p++) {
        int r = __ldg(&g_csr[p]);
        acc_add8(acc, __ldg(&base[(size_t)r * 32 + lane]));
    }

    const float sc = g_dinv[node];
    float* dst = &g_h1[(size_t)node * 256 + lane * 8];
    const float* bb = &bias[lane * 8];
#pragma unroll
    for (int q = 0; q < 2; q++) {
        float4 o;
        o.x = fmaf(acc[q * 4 + 0], sc, bb[q * 4 + 0]);
        o.y = fmaf(acc[q * 4 + 1], sc, bb[q * 4 + 1]);
        o.z = fmaf(acc[q * 4 + 2], sc, bb[q * 4 + 2]);
        o.w = fmaf(acc[q * 4 + 3], sc, bb[q * 4 + 3]);
        if (RELU) {
            o.x = fmaxf(o.x, 0.f); o.y = fmaxf(o.y, 0.f);
            o.z = fmaxf(o.z, 0.f); o.w = fmaxf(o.w, 0.f);
        }
        *(float4*)&dst[q * 4] = o;
    }
}

// D = 64: lane owns 2 cols (one half2). 8 warps/block.
template <int RELU>
__global__ void __launch_bounds__(256) agg64_k(const float* __restrict__ bias) {
    const int node = blockIdx.x * 8 + (threadIdx.x >> 5);
    if (node >= NN) return;
    const int lane = threadIdx.x & 31;
    const __half2* base = (const __half2*)g_h0h;  // row stride = 32 half2

    float2 acc = __half22float2(__ldg(&base[(size_t)node * 32 + lane]));

    const int s = g_off[node], e = g_off[node + 1];
    int p = s;
    for (; p + 4 <= e; p += 4) {
        int r0 = __ldg(&g_csr[p]);
        int r1 = __ldg(&g_csr[p + 1]);
        int r2 = __ldg(&g_csr[p + 2]);
        int r3 = __ldg(&g_csr[p + 3]);
        float2 f0 = __half22float2(__ldg(&base[(size_t)r0 * 32 + lane]));
        float2 f1 = __half22float2(__ldg(&base[(size_t)r1 * 32 + lane]));
        float2 f2 = __half22float2(__ldg(&base[(size_t)r2 * 32 + lane]));
        float2 f3 = __half22float2(__ldg(&base[(size_t)r3 * 32 + lane]));
        acc.x += f0.x + f1.x + f2.x + f3.x;
        acc.y += f0.y + f1.y + f2.y + f3.y;
    }
    for (; p < e; p++) {
        int r = __ldg(&g_csr[p]);
        float2 f = __half22float2(__ldg(&base[(size_t)r * 32 + lane]));
        acc.x += f.x; acc.y += f.y;
    }

    const float sc = g_dinv[node];
    float2 o;
    o.x = fmaf(acc.x, sc, bias[lane * 2]);
    o.y = fmaf(acc.y, sc, bias[lane * 2 + 1]);
    if (RELU) { o.x = fmaxf(o.x, 0.f); o.y = fmaxf(o.y, 0.f); }
    *(float2*)&g_h1[(size_t)node * 64 + lane * 2] = o;
}

// ---------------- final dense 64->64 + sigmoid (SIMT, tiny) ----------------
template <int BM, int BN, int TM, int TN, int KT, int KD>
__global__ void gemm_sig_k(const float* __restrict__ B, const float* __restrict__ bias,
                           float* __restrict__ C, int nrows, int mcols) {
    const float* A = (const float*)g_h1;
    __shared__ float As[BM][KT];
    __shared__ float Bs[KT][BN];

    const int tid = threadIdx.x;
    const int NTX = BN / TN;
    const int tx = tid % NTX;
    const int ty = tid / NTX;
    const int row0 = blockIdx.y * BM;
    const int col0 = blockIdx.x * BN;

    float acc[TM][TN];
#pragma unroll
    for (int i = 0; i < TM; i++)
#pragma unroll
        for (int j = 0; j < TN; j++) acc[i][j] = 0.0f;

    const int PA4 = (BM * KT) / (256 * 4);
    const int PB4 = (KT * BN) / (256 * 4);

    for (int k0 = 0; k0 < KD; k0 += KT) {
#pragma unroll
        for (int l = 0; l < PA4; l++) {
            int f = (tid + l * 256) * 4;
            int r = f / KT, kk = f % KT;
            float4 v = make_float4(0.f, 0.f, 0.f, 0.f);
            if (row0 + r < nrows)
                v = *(const float4*)&A[(size_t)(row0 + r) * KD + k0 + kk];
            *(float4*)&As[r][kk] = v;
        }
#pragma unroll
        for (int l = 0; l < PB4; l++) {
            int f = (tid + l * 256) * 4;
            int r = f / BN, cc = f % BN;
            *(float4*)&Bs[r][cc] = *(const float4*)&B[(size_t)(k0 + r) * mcols + col0 + cc];
        }
        __syncthreads();
#pragma unroll
        for (int k = 0; k < KT; k++) {
            float a[TM], b[TN];
#pragma unroll
            for (int i = 0; i < TM; i++) a[i] = As[ty * TM + i][k];
#pragma unroll
            for (int j = 0; j < TN; j++) b[j] = Bs[k][tx * TN + j];
#pragma unroll
            for (int i = 0; i < TM; i++)
#pragma unroll
                for (int j = 0; j < TN; j++) acc[i][j] = fmaf(a[i], b[j], acc[i][j]);
        }
        __syncthreads();
    }

#pragma unroll
    for (int i = 0; i < TM; i++) {
        int r = row0 + ty * TM + i;
        if (r >= nrows) continue;
#pragma unroll
        for (int j = 0; j < TN; j++) {
            int c = col0 + tx * TN + j;
            float v = acc[i][j] + bias[c];
            C[(size_t)r * mcols + c] = 1.0f / (1.0f + expf(-v));
        }
    }
}

// ---------------- launch ----------------
extern "C" void kernel_launch(void* const* d_in, const int* in_sizes, int n_in,
                              void* d_out, int out_size) {
    const float* x  = (const float*)d_in[0];
    const int* eiw  = (const int*)d_in[1];
    const float* W1 = (const float*)d_in[2];
    const float* b1 = (const float*)d_in[3];
    const float* W2 = (const float*)d_in[4];
    const float* b2 = (const float*)d_in[5];
    const float* W3 = (const float*)d_in[6];
    const float* b3 = (const float*)d_in[7];
    const float* W4 = (const float*)d_in[8];
    const float* b4 = (const float*)d_in[9];

    detect_k<<<1, 256>>>(eiw);
    zero_deg_k<<<(NN + 255) / 256, 256>>>();
    convert_count_k<<<(2 * EE + 255) / 256, 256>>>(eiw);
    scan_k<<<1, 1024>>>();
    scatter_k<<<(EE + 255) / 256, 256>>>();
    transpose_w_k<<<256, 256>>>(W1, W2, W3);

    const int MT = (NN + 127) / 128;       // 391
    const dim3 gBig(DH / 128, MT);         // (2, 391)
    const dim3 gS(1, MT);                  // (1, 391)
    const int AG = (NN + 7) / 8;           // 6250 blocks, warp per node

    // Layer 1: 256 -> 256, relu
    mma_gemm_k<128, 32, DH, 1><<<gBig, 256>>>(x, 0);
    agg256_k<1><<<AG, 256>>>(b1);

    // Layer 2 x4 (shared weights), relu
    for (int it = 0; it < 4; it++) {
        mma_gemm_k<128, 32, DH, 0><<<gBig, 256>>>(nullptr, 1);
        agg256_k<1><<<AG, 256>>>(b2);
    }

    // Layer 3: 256 -> 64, no relu
    mma_gemm_k<64, 16, DC, 0><<<gS, 256>>>(nullptr, 2);
    agg64_k<0><<<AG, 256>>>(b3);

    // Final dense 64 -> 64 + sigmoid
    gemm_sig_k<128, 64, 8, 4, 16, 64><<<gS, 256>>>(W4, b4, (float*)d_out, NN, DC);
}

// round 7
// speedup vs baseline: 2.3963x; 1.1376x over previous
#include <cuda_runtime.h>
#include <cuda_fp16.h>
#include <math.h>
#include <stdint.h>

#define NN 50000
#define EE 800000
#define DH 256
#define DC 64
#define NB 196           // (NN + 255) / 256

// ---------------- device scratch ----------------
__device__ __half g_h0h[NN * DH];    // GEMM output (dinv-scaled, fp16) -> agg gather input
__device__ float  g_h1[NN * DH];     // agg output (fp32) -> next GEMM A
__device__ float  g_Wt1[DH * DH];    // W^T: [n][k], K contiguous
__device__ float  g_Wt2[DH * DH];
__device__ float  g_Wt3[DC * DH];
__device__ float  g_dinv[NN];
__device__ int    g_deg[NN];
__device__ int    g_off[NN + 1];
__device__ int    g_cur[NN];
__device__ int    g_csr[EE];
__device__ int    g_idx[2 * EE];
__device__ int    g_part[256];
__device__ int    g_is64;

// ---------------- PTX helpers (sm_80-era, plain-sm_103-legal) ----------------
__device__ __forceinline__ uint32_t s2u(const void* p) {
    uint32_t a;
    asm("{ .reg .u64 t; cvta.to.shared.u64 t, %1; cvt.u32.u64 %0, t; }" : "=r"(a) : "l"(p));
    return a;
}
__device__ __forceinline__ void cp16(uint32_t dst, const void* src, bool valid) {
    int sz = valid ? 16 : 0;
    asm volatile("cp.async.ca.shared.global [%0], [%1], 16, %2;"
                 :: "r"(dst), "l"(src), "r"(sz) : "memory");
}
__device__ __forceinline__ void cp_commit() {
    asm volatile("cp.async.commit_group;" ::: "memory");
}
template <int N>
__device__ __forceinline__ void cp_wait() {
    asm volatile("cp.async.wait_group %0;" :: "n"(N) : "memory");
}
__device__ __forceinline__ void mma16n8k8(float* c, const uint32_t* a, const uint32_t* b) {
    asm volatile(
        "mma.sync.aligned.m16n8k8.row.col.f32.tf32.tf32.f32 "
        "{%0,%1,%2,%3}, {%4,%5,%6,%7}, {%8,%9}, {%0,%1,%2,%3};"
        : "+f"(c[0]), "+f"(c[1]), "+f"(c[2]), "+f"(c[3])
        : "r"(a[0]), "r"(a[1]), "r"(a[2]), "r"(a[3]), "r"(b[0]), "r"(b[1]));
}

// ---------------- edge-index dtype detection + normalization ----------------
__global__ void detect_k(const int* __restrict__ w) {
    __shared__ int any;
    if (threadIdx.x == 0) any = 0;
    __syncthreads();
    if (w[2 * threadIdx.x + 1] != 0) atomicOr(&any, 1);
    __syncthreads();
    if (threadIdx.x == 0) g_is64 = (any == 0) ? 1 : 0;
}
__global__ void zero_deg_k() {
    int i = blockIdx.x * blockDim.x + threadIdx.x;
    if (i < NN) g_deg[i] = 0;
}
// convert + fused degree count (for col entries)
__global__ void convert_count_k(const int* __restrict__ w) {
    int e = blockIdx.x * blockDim.x + threadIdx.x;
    if (e < 2 * EE) {
        int v = g_is64 ? w[2 * e] : w[e];
        if (v < 0) v = 0;
        if (v >= NN) v = NN - 1;
        g_idx[e] = v;
        if (e >= EE) atomicAdd(&g_deg[v], 1);
    }
}

// ---------------- parallel prefix sum (3 small kernels) ----------------
__global__ void block_reduce_k() {           // grid NB, block 256
    __shared__ int sm[256];
    int i = blockIdx.x * 256 + threadIdx.x;
    sm[threadIdx.x] = (i < NN) ? g_deg[i] : 0;
    __syncthreads();
#pragma unroll
    for (int d = 128; d > 0; d >>= 1) {
        if (threadIdx.x < d) sm[threadIdx.x] += sm[threadIdx.x + d];
        __syncthreads();
    }
    if (threadIdx.x == 0) g_part[blockIdx.x] = sm[0];
}
__global__ void scan_part_k() {              // 1 block, 256 threads
    __shared__ int sm[256];
    int t = threadIdx.x;
    int v = (t < NB) ? g_part[t] : 0;
    sm[t] = v;
    __syncthreads();
#pragma unroll
    for (int d = 1; d < 256; d <<= 1) {
        int u = (t >= d) ? sm[t - d] : 0;
        __syncthreads();
        sm[t] += u;
        __syncthreads();
    }
    g_part[t] = sm[t] - v;                   // exclusive
}
__global__ void write_off_k() {              // grid NB, block 256
    __shared__ int sm[256];
    int t = threadIdx.x;
    int i = blockIdx.x * 256 + t;
    int deg = (i < NN) ? g_deg[i] : 0;
    sm[t] = deg;
    __syncthreads();
#pragma unroll
    for (int d = 1; d < 256; d <<= 1) {
        int u = (t >= d) ? sm[t - d] : 0;
        __syncthreads();
        sm[t] += u;
        __syncthreads();
    }
    int base = g_part[blockIdx.x];
    int excl = base + sm[t] - deg;
    if (i < NN) {
        g_off[i] = excl;
        g_cur[i] = excl;
        g_dinv[i] = rsqrtf((float)(deg + 1));
        if (i == NN - 1) g_off[NN] = excl + deg;
    }
}

__global__ void scatter_k() {
    int e = blockIdx.x * blockDim.x + threadIdx.x;
    if (e < EE) {
        int c = g_idx[EE + e];
        int p = atomicAdd(&g_cur[c], 1);
        if (p < EE) g_csr[p] = g_idx[e];
    }
}

// ---------------- weight pre-transpose ----------------
__global__ void transpose_w_k(const float* __restrict__ W1, const float* __restrict__ W2,
                              const float* __restrict__ W3) {
    int i = blockIdx.x * blockDim.x + threadIdx.x;
    if (i < DH * DH) {
        int n = i / DH, k = i % DH;
        g_Wt1[i] = W1[k * DH + n];
        g_Wt2[i] = W2[k * DH + n];
    }
    if (i < DC * DH) {
        int n = i / DH, k = i % DH;
        g_Wt3[i] = W3[k * DC + n];
    }
}

// ---------------- tf32 mma.sync GEMM, fp16 epilogue ----------------
template <int BN, int WN, int MCOLS, int EXT_A>
__global__ void __launch_bounds__(256) mma_gemm_k(const float* __restrict__ A_ext, int wsel) {
    const float* A = EXT_A ? A_ext : (const float*)g_h1;
    const float* Bt = (wsel == 0) ? (const float*)g_Wt1
                    : (wsel == 1) ? (const float*)g_Wt2
                                  : (const float*)g_Wt3;

    constexpr int ST = 20;
    constexpr int NT = WN / 8;
    __shared__ float As[2][128 * ST];
    __shared__ float Bs[2][BN * ST];

    const int tid = threadIdx.x;
    const int wid = tid >> 5;
    const int lane = tid & 31;
    const int t4 = lane >> 2;
    const int tk = lane & 3;
    const int wm = wid & 1;
    const int wn = wid >> 1;
    const int row0 = blockIdx.y * 128;
    const int col0 = blockIdx.x * BN;

    float c[4][NT][4];
#pragma unroll
    for (int mt = 0; mt < 4; mt++)
#pragma unroll
        for (int nt = 0; nt < NT; nt++)
#pragma unroll
            for (int j = 0; j < 4; j++) c[mt][nt][j] = 0.0f;

    const uint32_t sa[2] = { s2u(As[0]), s2u(As[1]) };
    const uint32_t sb[2] = { s2u(Bs[0]), s2u(Bs[1]) };

    auto load_chunk = [&](int kc, int st) {
#pragma unroll
        for (int i = 0; i < 2; i++) {
            int l = tid + i * 256;
            int m = l >> 2, k = (l & 3) * 4;
            bool v = (row0 + m) < NN;
            cp16(sa[st] + (uint32_t)(m * ST + k) * 4,
                 &A[(size_t)(row0 + m) * DH + kc * 16 + k], v);
        }
#pragma unroll
        for (int i = 0; i < BN / 64; i++) {
            int l = tid + i * 256;
            int n = l >> 2, k = (l & 3) * 4;
            cp16(sb[st] + (uint32_t)(n * ST + k) * 4,
                 &Bt[(size_t)(col0 + n) * DH + kc * 16 + k], true);
        }
        cp_commit();
    };

    load_chunk(0, 0);

    for (int kc = 0; kc < 16; kc++) {
        const int st = kc & 1;
        if (kc + 1 < 16) {
            load_chunk(kc + 1, st ^ 1);
            cp_wait<1>();
        } else {
            cp_wait<0>();
        }
        __syncthreads();

        const float* as = As[st];
        const float* bs = Bs[st];
#pragma unroll
        for (int ks = 0; ks < 2; ks++) {
            const int k0 = ks * 8;
            uint32_t a[4][4];
#pragma unroll
            for (int mt = 0; mt < 4; mt++) {
                int m = wm * 64 + mt * 16 + t4;
                a[mt][0] = __float_as_uint(as[m * ST + k0 + tk]);
                a[mt][1] = __float_as_uint(as[(m + 8) * ST + k0 + tk]);
                a[mt][2] = __float_as_uint(as[m * ST + k0 + tk + 4]);
                a[mt][3] = __float_as_uint(as[(m + 8) * ST + k0 + tk + 4]);
            }
            uint32_t b[NT][2];
#pragma unroll
            for (int nt = 0; nt < NT; nt++) {
                int n = wn * WN + nt * 8 + t4;
                b[nt][0] = __float_as_uint(bs[n * ST + k0 + tk]);
                b[nt][1] = __float_as_uint(bs[n * ST + k0 + tk + 4]);
            }
#pragma unroll
            for (int mt = 0; mt < 4; mt++)
#pragma unroll
                for (int nt = 0; nt < NT; nt++)
                    mma16n8k8(c[mt][nt], a[mt], b[nt]);
        }
        __syncthreads();
    }

#pragma unroll
    for (int mt = 0; mt < 4; mt++) {
        int r0g = row0 + wm * 64 + mt * 16 + t4;
        int r1g = r0g + 8;
        float s0 = (r0g < NN) ? g_dinv[r0g] : 0.0f;
        float s1 = (r1g < NN) ? g_dinv[r1g] : 0.0f;
#pragma unroll
        for (int nt = 0; nt < NT; nt++) {
            int gc = col0 + wn * WN + nt * 8 + 2 * tk;
            if (r0g < NN)
                *(__half2*)&g_h0h[(size_t)r0g * MCOLS + gc] =
                    __floats2half2_rn(c[mt][nt][0] * s0, c[mt][nt][1] * s0);
            if (r1g < NN)
                *(__half2*)&g_h0h[(size_t)r1g * MCOLS + gc] =
                    __floats2half2_rn(c[mt][nt][2] * s1, c[mt][nt][3] * s1);
        }
    }
}

// ---------------- aggregation (warp per node, fp16 gather, fp32 accum) ----------------
__device__ __forceinline__ void acc_add8(float* acc, uint4 v) {
    const __half2* h = (const __half2*)&v;
#pragma unroll
    for (int i = 0; i < 4; i++) {
        float2 f = __half22float2(h[i]);
        acc[2 * i] += f.x;
        acc[2 * i + 1] += f.y;
    }
}

// D = 256: lane owns 8 contiguous cols (one uint4 of halves). 8 warps/block.
template <int RELU>
__global__ void __launch_bounds__(256) agg256_k(const float* __restrict__ bias) {
    const int node = blockIdx.x * 8 + (threadIdx.x >> 5);
    if (node >= NN) return;
    const int lane = threadIdx.x & 31;
    const uint4* base = (const uint4*)g_h0h;   // row stride = 32 uint4

    float acc[8];
    uint4 v = __ldg(&base[(size_t)node * 32 + lane]);   // self loop
#pragma unroll
    for (int i = 0; i < 8; i++) acc[i] = 0.0f;
    acc_add8(acc, v);

    const int s = g_off[node], e = g_off[node + 1];
    int p = s;
    // unroll 8: 8 independent row gathers in flight
    for (; p + 8 <= e; p += 8) {
        int r[8];
#pragma unroll
        for (int j = 0; j < 8; j++) r[j] = __ldg(&g_csr[p + j]);
        uint4 vv[8];
#pragma unroll
        for (int j = 0; j < 8; j++) vv[j] = __ldg(&base[(size_t)r[j] * 32 + lane]);
#pragma unroll
        for (int j = 0; j < 8; j++) acc_add8(acc, vv[j]);
    }
    for (; p + 4 <= e; p += 4) {
        int r0 = __ldg(&g_csr[p]);
        int r1 = __ldg(&g_csr[p + 1]);
        int r2 = __ldg(&g_csr[p + 2]);
        int r3 = __ldg(&g_csr[p + 3]);
        uint4 v0 = __ldg(&base[(size_t)r0 * 32 + lane]);
        uint4 v1 = __ldg(&base[(size_t)r1 * 32 + lane]);
        uint4 v2 = __ldg(&base[(size_t)r2 * 32 + lane]);
        uint4 v3 = __ldg(&base[(size_t)r3 * 32 + lane]);
        acc_add8(acc, v0); acc_add8(acc, v1); acc_add8(acc, v2); acc_add8(acc, v3);
    }
    for (; p < e; p++) {
        int r = __ldg(&g_csr[p]);
        acc_add8(acc, __ldg(&base[(size_t)r * 32 + lane]));
    }

    const float sc = g_dinv[node];
    float* dst = &g_h1[(size_t)node * 256 + lane * 8];
    const float* bb = &bias[lane * 8];
#pragma unroll
    for (int q = 0; q < 2; q++) {
        float4 o;
        o.x = fmaf(acc[q * 4 + 0], sc, bb[q * 4 + 0]);
        o.y = fmaf(acc[q * 4 + 1], sc, bb[q * 4 + 1]);
        o.z = fmaf(acc[q * 4 + 2], sc, bb[q * 4 + 2]);
        o.w = fmaf(acc[q * 4 + 3], sc, bb[q * 4 + 3]);
        if (RELU) {
            o.x = fmaxf(o.x, 0.f); o.y = fmaxf(o.y, 0.f);
            o.z = fmaxf(o.z, 0.f); o.w = fmaxf(o.w, 0.f);
        }
        *(float4*)&dst[q * 4] = o;
    }
}

// D = 64: lane owns 2 cols (one half2). 8 warps/block.
template <int RELU>
__global__ void __launch_bounds__(256) agg64_k(const float* __restrict__ bias) {
    const int node = blockIdx.x * 8 + (threadIdx.x >> 5);
    if (node >= NN) return;
    const int lane = threadIdx.x & 31;
    const __half2* base = (const __half2*)g_h0h;  // row stride = 32 half2

    float2 acc = __half22float2(__ldg(&base[(size_t)node * 32 + lane]));

    const int s = g_off[node], e = g_off[node + 1];
    int p = s;
    for (; p + 8 <= e; p += 8) {
        int r[8];
#pragma unroll
        for (int j = 0; j < 8; j++) r[j] = __ldg(&g_csr[p + j]);
        float2 f[8];
#pragma unroll
        for (int j = 0; j < 8; j++) f[j] = __half22float2(__ldg(&base[(size_t)r[j] * 32 + lane]));
#pragma unroll
        for (int j = 0; j < 8; j++) { acc.x += f[j].x; acc.y += f[j].y; }
    }
    for (; p < e; p++) {
        int r = __ldg(&g_csr[p]);
        float2 f = __half22float2(__ldg(&base[(size_t)r * 32 + lane]));
        acc.x += f.x; acc.y += f.y;
    }

    const float sc = g_dinv[node];
    float2 o;
    o.x = fmaf(acc.x, sc, bias[lane * 2]);
    o.y = fmaf(acc.y, sc, bias[lane * 2 + 1]);
    if (RELU) { o.x = fmaxf(o.x, 0.f); o.y = fmaxf(o.y, 0.f); }
    *(float2*)&g_h1[(size_t)node * 64 + lane * 2] = o;
}

// ---------------- final dense 64->64 + sigmoid (SIMT, tiny) ----------------
template <int BM, int BN, int TM, int TN, int KT, int KD>
__global__ void gemm_sig_k(const float* __restrict__ B, const float* __restrict__ bias,
                           float* __restrict__ C, int nrows, int mcols) {
    const float* A = (const float*)g_h1;
    __shared__ float As[BM][KT];
    __shared__ float Bs[KT][BN];

    const int tid = threadIdx.x;
    const int NTX = BN / TN;
    const int tx = tid % NTX;
    const int ty = tid / NTX;
    const int row0 = blockIdx.y * BM;
    const int col0 = blockIdx.x * BN;

    float acc[TM][TN];
#pragma unroll
    for (int i = 0; i < TM; i++)
#pragma unroll
        for (int j = 0; j < TN; j++) acc[i][j] = 0.0f;

    const int PA4 = (BM * KT) / (256 * 4);
    const int PB4 = (KT * BN) / (256 * 4);

    for (int k0 = 0; k0 < KD; k0 += KT) {
#pragma unroll
        for (int l = 0; l < PA4; l++) {
            int f = (tid + l * 256) * 4;
            int r = f / KT, kk = f % KT;
            float4 v = make_float4(0.f, 0.f, 0.f, 0.f);
            if (row0 + r < nrows)
                v = *(const float4*)&A[(size_t)(row0 + r) * KD + k0 + kk];
            *(float4*)&As[r][kk] = v;
        }
#pragma unroll
        for (int l = 0; l < PB4; l++) {
            int f = (tid + l * 256) * 4;
            int r = f / BN, cc = f % BN;
            *(float4*)&Bs[r][cc] = *(const float4*)&B[(size_t)(k0 + r) * mcols + col0 + cc];
        }
        __syncthreads();
#pragma unroll
        for (int k = 0; k < KT; k++) {
            float a[TM], b[TN];
#pragma unroll
            for (int i = 0; i < TM; i++) a[i] = As[ty * TM + i][k];
#pragma unroll
            for (int j = 0; j < TN; j++) b[j] = Bs[k][tx * TN + j];
#pragma unroll
            for (int i = 0; i < TM; i++)
#pragma unroll
                for (int j = 0; j < TN; j++) acc[i][j] = fmaf(a[i], b[j], acc[i][j]);
        }
        __syncthreads();
    }

#pragma unroll
    for (int i = 0; i < TM; i++) {
        int r = row0 + ty * TM + i;
        if (r >= nrows) continue;
#pragma unroll
        for (int j = 0; j < TN; j++) {
            int c = col0 + tx * TN + j;
            float v = acc[i][j] + bias[c];
            C[(size_t)r * mcols + c] = 1.0f / (1.0f + expf(-v));
        }
    }
}

// ---------------- launch ----------------
extern "C" void kernel_launch(void* const* d_in, const int* in_sizes, int n_in,
                              void* d_out, int out_size) {
    const float* x  = (const float*)d_in[0];
    const int* eiw  = (const int*)d_in[1];
    const float* W1 = (const float*)d_in[2];
    const float* b1 = (const float*)d_in[3];
    const float* W2 = (const float*)d_in[4];
    const float* b2 = (const float*)d_in[5];
    const float* W3 = (const float*)d_in[6];
    const float* b3 = (const float*)d_in[7];
    const float* W4 = (const float*)d_in[8];
    const float* b4 = (const float*)d_in[9];

    detect_k<<<1, 256>>>(eiw);
    zero_deg_k<<<(NN + 255) / 256, 256>>>();
    convert_count_k<<<(2 * EE + 255) / 256, 256>>>(eiw);
    block_reduce_k<<<NB, 256>>>();
    scan_part_k<<<1, 256>>>();
    write_off_k<<<NB, 256>>>();
    scatter_k<<<(EE + 255) / 256, 256>>>();
    transpose_w_k<<<256, 256>>>(W1, W2, W3);

    const int MT = (NN + 127) / 128;       // 391
    const dim3 gBig(DH / 128, MT);         // (2, 391)
    const dim3 gS(1, MT);                  // (1, 391)
    const int AG = (NN + 7) / 8;           // 6250 blocks, warp per node

    // Layer 1: 256 -> 256, relu
    mma_gemm_k<128, 32, DH, 1><<<gBig, 256>>>(x, 0);
    agg256_k<1><<<AG, 256>>>(b1);

    // Layer 2 x4 (shared weights), relu
    for (int it = 0; it < 4; it++) {
        mma_gemm_k<128, 32, DH, 0><<<gBig, 256>>>(nullptr, 1);
        agg256_k<1><<<AG, 256>>>(b2);
    }

    // Layer 3: 256 -> 64, no relu
    mma_gemm_k<64, 16, DC, 0><<<gS, 256>>>(nullptr, 2);
    agg64_k<0><<<AG, 256>>>(b3);

    // Final dense 64 -> 64 + sigmoid
    gemm_sig_k<128, 64, 8, 4, 16, 64><<<gS, 256>>>(W4, b4, (float*)d_out, NN, DC);
}

// round 8
// speedup vs baseline: 3.2074x; 1.3384x over previous
#include <cuda_runtime.h>
#include <cuda_fp16.h>
#include <math.h>
#include <stdint.h>

#define NN 50000
#define EE 800000
#define DH 256
#define DC 64
#define NB 196           // (NN + 255) / 256

// ---------------- device scratch ----------------
__device__ __half g_h0h[NN * DH];    // GEMM output (dinv-scaled, fp16) -> agg gather input
__device__ __half g_h1h[NN * DH];    // agg output (fp16) -> next GEMM A
__device__ __half g_xh[NN * DH];     // input features converted to fp16
__device__ __half g_Wt1h[DH * DH];   // W^T fp16: [n][k], K contiguous
__device__ __half g_Wt2h[DH * DH];
__device__ __half g_Wt3h[DC * DH];
__device__ float  g_dinv[NN];
__device__ int    g_deg[NN];
__device__ int    g_off[NN + 1];
__device__ int    g_cur[NN];
__device__ int    g_csr[EE];
__device__ int    g_idx[2 * EE];
__device__ int    g_part[256];
__device__ int    g_is64;

// ---------------- PTX helpers (sm_80-era, plain-sm_103-legal) ----------------
__device__ __forceinline__ uint32_t s2u(const void* p) {
    uint32_t a;
    asm("{ .reg .u64 t; cvta.to.shared.u64 t, %1; cvt.u32.u64 %0, t; }" : "=r"(a) : "l"(p));
    return a;
}
__device__ __forceinline__ void cp16(uint32_t dst, const void* src, bool valid) {
    int sz = valid ? 16 : 0;
    asm volatile("cp.async.ca.shared.global [%0], [%1], 16, %2;"
                 :: "r"(dst), "l"(src), "r"(sz) : "memory");
}
__device__ __forceinline__ void cp_commit() {
    asm volatile("cp.async.commit_group;" ::: "memory");
}
template <int N>
__device__ __forceinline__ void cp_wait() {
    asm volatile("cp.async.wait_group %0;" :: "n"(N) : "memory");
}
__device__ __forceinline__ void mma16n8k16(float* c, const uint32_t* a, const uint32_t* b) {
    asm volatile(
        "mma.sync.aligned.m16n8k16.row.col.f32.f16.f16.f32 "
        "{%0,%1,%2,%3}, {%4,%5,%6,%7}, {%8,%9}, {%0,%1,%2,%3};"
        : "+f"(c[0]), "+f"(c[1]), "+f"(c[2]), "+f"(c[3])
        : "r"(a[0]), "r"(a[1]), "r"(a[2]), "r"(a[3]), "r"(b[0]), "r"(b[1]));
}

// ---------------- edge-index dtype detection + normalization ----------------
__global__ void detect_k(const int* __restrict__ w) {
    __shared__ int any;
    if (threadIdx.x == 0) any = 0;
    __syncthreads();
    if (w[2 * threadIdx.x + 1] != 0) atomicOr(&any, 1);
    __syncthreads();
    if (threadIdx.x == 0) g_is64 = (any == 0) ? 1 : 0;
}
__global__ void zero_deg_k() {
    int i = blockIdx.x * blockDim.x + threadIdx.x;
    if (i < NN) g_deg[i] = 0;
}
__global__ void convert_count_k(const int* __restrict__ w) {
    int e = blockIdx.x * blockDim.x + threadIdx.x;
    if (e < 2 * EE) {
        int v = g_is64 ? w[2 * e] : w[e];
        if (v < 0) v = 0;
        if (v >= NN) v = NN - 1;
        g_idx[e] = v;
        if (e >= EE) atomicAdd(&g_deg[v], 1);
    }
}

// ---------------- parallel prefix sum ----------------
__global__ void block_reduce_k() {
    __shared__ int sm[256];
    int i = blockIdx.x * 256 + threadIdx.x;
    sm[threadIdx.x] = (i < NN) ? g_deg[i] : 0;
    __syncthreads();
#pragma unroll
    for (int d = 128; d > 0; d >>= 1) {
        if (threadIdx.x < d) sm[threadIdx.x] += sm[threadIdx.x + d];
        __syncthreads();
    }
    if (threadIdx.x == 0) g_part[blockIdx.x] = sm[0];
}
__global__ void scan_part_k() {
    __shared__ int sm[256];
    int t = threadIdx.x;
    int v = (t < NB) ? g_part[t] : 0;
    sm[t] = v;
    __syncthreads();
#pragma unroll
    for (int d = 1; d < 256; d <<= 1) {
        int u = (t >= d) ? sm[t - d] : 0;
        __syncthreads();
        sm[t] += u;
        __syncthreads();
    }
    g_part[t] = sm[t] - v;
}
__global__ void write_off_k() {
    __shared__ int sm[256];
    int t = threadIdx.x;
    int i = blockIdx.x * 256 + t;
    int deg = (i < NN) ? g_deg[i] : 0;
    sm[t] = deg;
    __syncthreads();
#pragma unroll
    for (int d = 1; d < 256; d <<= 1) {
        int u = (t >= d) ? sm[t - d] : 0;
        __syncthreads();
        sm[t] += u;
        __syncthreads();
    }
    int base = g_part[blockIdx.x];
    int excl = base + sm[t] - deg;
    if (i < NN) {
        g_off[i] = excl;
        g_cur[i] = excl;
        g_dinv[i] = rsqrtf((float)(deg + 1));
        if (i == NN - 1) g_off[NN] = excl + deg;
    }
}
__global__ void scatter_k() {
    int e = blockIdx.x * blockDim.x + threadIdx.x;
    if (e < EE) {
        int c = g_idx[EE + e];
        int p = atomicAdd(&g_cur[c], 1);
        if (p < EE) g_csr[p] = g_idx[e];
    }
}

// ---------------- weight transpose+fp16, x -> fp16 ----------------
__global__ void transpose_w_k(const float* __restrict__ W1, const float* __restrict__ W2,
                              const float* __restrict__ W3) {
    int i = blockIdx.x * blockDim.x + threadIdx.x;
    if (i < DH * DH) {
        int n = i / DH, k = i % DH;
        g_Wt1h[i] = __float2half(W1[k * DH + n]);
        g_Wt2h[i] = __float2half(W2[k * DH + n]);
    }
    if (i < DC * DH) {
        int n = i / DH, k = i % DH;
        g_Wt3h[i] = __float2half(W3[k * DC + n]);
    }
}
__global__ void convert_x_k(const float* __restrict__ x) {
    int i = blockIdx.x * blockDim.x + threadIdx.x;
    if (i < NN * DH) {
        float2 v = *(const float2*)&x[2 * i];
        ((__half2*)g_xh)[i] = __floats2half2_rn(v.x, v.y);
    }
}

// ---------------- fp16 mma.sync GEMM (m16n8k16), fp16 epilogue ----------------
// g_h0h[NN, MCOLS] = (A[NN, 256] @ Wt^T) * dinv[row].
// CTA 128 x BN, 8 warps 2(m) x 4(n), warp tile 64 x WN. K = 256 in 8 chunks of 32,
// cp.async double-buffered. SMEM stride 40 halves -> conflict-free half2 LDS.
template <int BN, int WN, int MCOLS, int ASEL>
__global__ void __launch_bounds__(256) mma_gemm_k(int wsel) {
    const __half* A = (ASEL == 0) ? (const __half*)g_xh : (const __half*)g_h1h;
    const __half* Bt = (wsel == 0) ? (const __half*)g_Wt1h
                     : (wsel == 1) ? (const __half*)g_Wt2h
                                   : (const __half*)g_Wt3h;

    constexpr int ST = 40;            // halves
    constexpr int NT = WN / 8;
    __shared__ __half As[2][128 * ST];
    __shared__ __half Bs[2][BN * ST];

    const int tid = threadIdx.x;
    const int wid = tid >> 5;
    const int lane = tid & 31;
    const int t4 = lane >> 2;
    const int tk = lane & 3;
    const int wm = wid & 1;
    const int wn = wid >> 1;
    const int row0 = blockIdx.y * 128;
    const int col0 = blockIdx.x * BN;

    float c[4][NT][4];
#pragma unroll
    for (int mt = 0; mt < 4; mt++)
#pragma unroll
        for (int nt = 0; nt < NT; nt++)
#pragma unroll
            for (int j = 0; j < 4; j++) c[mt][nt][j] = 0.0f;

    const uint32_t sa[2] = { s2u(As[0]), s2u(As[1]) };
    const uint32_t sb[2] = { s2u(Bs[0]), s2u(Bs[1]) };

    // chunk = 32 halves of K (64 B/row). A: 128 rows * 4 cp16; B: BN rows * 4 cp16.
    auto load_chunk = [&](int kc, int st) {
#pragma unroll
        for (int i = 0; i < 2; i++) {
            int l = tid + i * 256;
            int m = l >> 2, kq = l & 3;
            bool v = (row0 + m) < NN;
            cp16(sa[st] + (uint32_t)(m * ST + kq * 8) * 2,
                 &A[(size_t)(row0 + m) * DH + kc * 32 + kq * 8], v);
        }
#pragma unroll
        for (int i = 0; i < BN / 64; i++) {
            int l = tid + i * 256;
            int n = l >> 2, kq = l & 3;
            cp16(sb[st] + (uint32_t)(n * ST + kq * 8) * 2,
                 &Bt[(size_t)(col0 + n) * DH + kc * 32 + kq * 8], true);
        }
        cp_commit();
    };

    load_chunk(0, 0);

    for (int kc = 0; kc < 8; kc++) {
        const int st = kc & 1;
        if (kc + 1 < 8) {
            load_chunk(kc + 1, st ^ 1);
            cp_wait<1>();
        } else {
            cp_wait<0>();
        }
        __syncthreads();

        const __half* as = As[st];
        const __half* bs = Bs[st];
#pragma unroll
        for (int ks = 0; ks < 2; ks++) {
            const int k0 = ks * 16;
            uint32_t a[4][4];
#pragma unroll
            for (int mt = 0; mt < 4; mt++) {
                int m = wm * 64 + mt * 16 + t4;
                a[mt][0] = *(const uint32_t*)&as[m * ST + k0 + 2 * tk];
                a[mt][1] = *(const uint32_t*)&as[(m + 8) * ST + k0 + 2 * tk];
                a[mt][2] = *(const uint32_t*)&as[m * ST + k0 + 2 * tk + 8];
                a[mt][3] = *(const uint32_t*)&as[(m + 8) * ST + k0 + 2 * tk + 8];
            }
            uint32_t b[NT][2];
#pragma unroll
            for (int nt = 0; nt < NT; nt++) {
                int n = wn * WN + nt * 8 + t4;
                b[nt][0] = *(const uint32_t*)&bs[n * ST + k0 + 2 * tk];
                b[nt][1] = *(const uint32_t*)&bs[n * ST + k0 + 2 * tk + 8];
            }
#pragma unroll
            for (int mt = 0; mt < 4; mt++)
#pragma unroll
                for (int nt = 0; nt < NT; nt++)
                    mma16n8k16(c[mt][nt], a[mt], b[nt]);
        }
        __syncthreads();
    }

    // epilogue: scale by dinv, store fp16 pairs
#pragma unroll
    for (int mt = 0; mt < 4; mt++) {
        int r0g = row0 + wm * 64 + mt * 16 + t4;
        int r1g = r0g + 8;
        float s0 = (r0g < NN) ? g_dinv[r0g] : 0.0f;
        float s1 = (r1g < NN) ? g_dinv[r1g] : 0.0f;
#pragma unroll
        for (int nt = 0; nt < NT; nt++) {
            int gc = col0 + wn * WN + nt * 8 + 2 * tk;
            if (r0g < NN)
                *(__half2*)&g_h0h[(size_t)r0g * MCOLS + gc] =
                    __floats2half2_rn(c[mt][nt][0] * s0, c[mt][nt][1] * s0);
            if (r1g < NN)
                *(__half2*)&g_h0h[(size_t)r1g * MCOLS + gc] =
                    __floats2half2_rn(c[mt][nt][2] * s1, c[mt][nt][3] * s1);
        }
    }
}

// ---------------- aggregation (warp per node, fp16 gather, fp32 accum) ----------------
__device__ __forceinline__ void acc_add8(float* acc, uint4 v) {
    const __half2* h = (const __half2*)&v;
#pragma unroll
    for (int i = 0; i < 4; i++) {
        float2 f = __half22float2(h[i]);
        acc[2 * i] += f.x;
        acc[2 * i + 1] += f.y;
    }
}

// D = 256: lane owns 8 cols (uint4 of halves). 8 warps/block. Output fp16.
template <int RELU>
__global__ void __launch_bounds__(256) agg256_k(const float* __restrict__ bias) {
    const int node = blockIdx.x * 8 + (threadIdx.x >> 5);
    if (node >= NN) return;
    const int lane = threadIdx.x & 31;
    const uint4* base = (const uint4*)g_h0h;   // row stride 32 uint4

    float acc[8];
    uint4 v = __ldg(&base[(size_t)node * 32 + lane]);
#pragma unroll
    for (int i = 0; i < 8; i++) acc[i] = 0.0f;
    acc_add8(acc, v);

    const int s = g_off[node], e = g_off[node + 1];
    int p = s;
    for (; p + 8 <= e; p += 8) {
        int r[8];
#pragma unroll
        for (int j = 0; j < 8; j++) r[j] = __ldg(&g_csr[p + j]);
        uint4 vv[8];
#pragma unroll
        for (int j = 0; j < 8; j++) vv[j] = __ldg(&base[(size_t)r[j] * 32 + lane]);
#pragma unroll
        for (int j = 0; j < 8; j++) acc_add8(acc, vv[j]);
    }
    for (; p < e; p++) {
        int r = __ldg(&g_csr[p]);
        acc_add8(acc, __ldg(&base[(size_t)r * 32 + lane]));
    }

    const float sc = g_dinv[node];
    const float* bb = &bias[lane * 8];
    __half2 o[4];
#pragma unroll
    for (int q = 0; q < 4; q++) {
        float ox = fmaf(acc[2 * q], sc, bb[2 * q]);
        float oy = fmaf(acc[2 * q + 1], sc, bb[2 * q + 1]);
        if (RELU) { ox = fmaxf(ox, 0.f); oy = fmaxf(oy, 0.f); }
        o[q] = __floats2half2_rn(ox, oy);
    }
    *(uint4*)&g_h1h[(size_t)node * 256 + lane * 8] = *(uint4*)o;
}

// D = 64: lane owns 2 cols (half2). 8 warps/block. Output fp16.
template <int RELU>
__global__ void __launch_bounds__(256) agg64_k(const float* __restrict__ bias) {
    const int node = blockIdx.x * 8 + (threadIdx.x >> 5);
    if (node >= NN) return;
    const int lane = threadIdx.x & 31;
    const __half2* base = (const __half2*)g_h0h;  // row stride 32 half2

    float2 acc = __half22float2(__ldg(&base[(size_t)node * 32 + lane]));

    const int s = g_off[node], e = g_off[node + 1];
    int p = s;
    for (; p + 8 <= e; p += 8) {
        int r[8];
#pragma unroll
        for (int j = 0; j < 8; j++) r[j] = __ldg(&g_csr[p + j]);
        float2 f[8];
#pragma unroll
        for (int j = 0; j < 8; j++) f[j] = __half22float2(__ldg(&base[(size_t)r[j] * 32 + lane]));
#pragma unroll
        for (int j = 0; j < 8; j++) { acc.x += f[j].x; acc.y += f[j].y; }
    }
    for (; p < e; p++) {
        int r = __ldg(&g_csr[p]);
        float2 f = __half22float2(__ldg(&base[(size_t)r * 32 + lane]));
        acc.x += f.x; acc.y += f.y;
    }

    const float sc = g_dinv[node];
    float ox = fmaf(acc.x, sc, bias[lane * 2]);
    float oy = fmaf(acc.y, sc, bias[lane * 2 + 1]);
    if (RELU) { ox = fmaxf(ox, 0.f); oy = fmaxf(oy, 0.f); }
    ((__half2*)g_h1h)[(size_t)node * 32 + lane] = __floats2half2_rn(ox, oy);
}

// ---------------- final dense 64->64 + sigmoid (SIMT, tiny; fp16 A) ----------------
template <int BM, int BN, int TM, int TN, int KT, int KD>
__global__ void gemm_sig_k(const float* __restrict__ B, const float* __restrict__ bias,
                           float* __restrict__ C, int nrows, int mcols) {
    const __half* A = (const __half*)g_h1h;
    __shared__ float As[BM][KT];
    __shared__ float Bs[KT][BN];

    const int tid = threadIdx.x;
    const int NTX = BN / TN;
    const int tx = tid % NTX;
    const int ty = tid / NTX;
    const int row0 = blockIdx.y * BM;
    const int col0 = blockIdx.x * BN;

    float acc[TM][TN];
#pragma unroll
    for (int i = 0; i < TM; i++)
#pragma unroll
        for (int j = 0; j < TN; j++) acc[i][j] = 0.0f;

    const int PA4 = (BM * KT) / (256 * 4);
    const int PB4 = (KT * BN) / (256 * 4);

    for (int k0 = 0; k0 < KD; k0 += KT) {
#pragma unroll
        for (int l = 0; l < PA4; l++) {
            int f = (tid + l * 256) * 4;
            int r = f / KT, kk = f % KT;
            float4 v = make_float4(0.f, 0.f, 0.f, 0.f);
            if (row0 + r < nrows) {
                uint2 hw = *(const uint2*)&A[(size_t)(row0 + r) * KD + k0 + kk];
                float2 f01 = __half22float2(*(const __half2*)&hw.x);
                float2 f23 = __half22float2(*(const __half2*)&hw.y);
                v = make_float4(f01.x, f01.y, f23.x, f23.y);
            }
            *(float4*)&As[r][kk] = v;
        }
#pragma unroll
        for (int l = 0; l < PB4; l++) {
            int f = (tid + l * 256) * 4;
            int r = f / BN, cc = f % BN;
            *(float4*)&Bs[r][cc] = *(const float4*)&B[(size_t)(k0 + r) * mcols + col0 + cc];
        }
        __syncthreads();
#pragma unroll
        for (int k = 0; k < KT; k++) {
            float a[TM], b[TN];
#pragma unroll
            for (int i = 0; i < TM; i++) a[i] = As[ty * TM + i][k];
#pragma unroll
            for (int j = 0; j < TN; j++) b[j] = Bs[k][tx * TN + j];
#pragma unroll
            for (int i = 0; i < TM; i++)
#pragma unroll
                for (int j = 0; j < TN; j++) acc[i][j] = fmaf(a[i], b[j], acc[i][j]);
        }
        __syncthreads();
    }

#pragma unroll
    for (int i = 0; i < TM; i++) {
        int r = row0 + ty * TM + i;
        if (r >= nrows) continue;
#pragma unroll
        for (int j = 0; j < TN; j++) {
            int c = col0 + tx * TN + j;
            float v = acc[i][j] + bias[c];
            C[(size_t)r * mcols + c] = 1.0f / (1.0f + expf(-v));
        }
    }
}

// ---------------- launch ----------------
extern "C" void kernel_launch(void* const* d_in, const int* in_sizes, int n_in,
                              void* d_out, int out_size) {
    const float* x  = (const float*)d_in[0];
    const int* eiw  = (const int*)d_in[1];
    const float* W1 = (const float*)d_in[2];
    const float* b1 = (const float*)d_in[3];
    const float* W2 = (const float*)d_in[4];
    const float* b2 = (const float*)d_in[5];
    const float* W3 = (const float*)d_in[6];
    const float* b3 = (const float*)d_in[7];
    const float* W4 = (const float*)d_in[8];
    const float* b4 = (const float*)d_in[9];

    detect_k<<<1, 256>>>(eiw);
    zero_deg_k<<<(NN + 255) / 256, 256>>>();
    convert_count_k<<<(2 * EE + 255) / 256, 256>>>(eiw);
    block_reduce_k<<<NB, 256>>>();
    scan_part_k<<<1, 256>>>();
    write_off_k<<<NB, 256>>>();
    scatter_k<<<(EE + 255) / 256, 256>>>();
    transpose_w_k<<<256, 256>>>(W1, W2, W3);
    convert_x_k<<<(NN * DH / 2 + 255) / 256, 256>>>(x);

    const int MT = (NN + 127) / 128;       // 391
    const dim3 gBig(DH / 128, MT);         // (2, 391)
    const dim3 gS(1, MT);                  // (1, 391)
    const int AG = (NN + 7) / 8;

    // Layer 1: 256 -> 256, relu (A = converted x)
    mma_gemm_k<128, 32, DH, 0><<<gBig, 256>>>(0);
    agg256_k<1><<<AG, 256>>>(b1);

    // Layer 2 x4 (shared weights), relu
    for (int it = 0; it < 4; it++) {
        mma_gemm_k<128, 32, DH, 1><<<gBig, 256>>>(1);
        agg256_k<1><<<AG, 256>>>(b2);
    }

    // Layer 3: 256 -> 64, no relu
    mma_gemm_k<64, 16, DC, 1><<<gS, 256>>>(2);
    agg64_k<0><<<AG, 256>>>(b3);

    // Final dense 64 -> 64 + sigmoid
    gemm_sig_k<128, 64, 8, 4, 16, 64><<<gS, 256>>>(W4, b4, (float*)d_out, NN, DC);
}